// round 9
// baseline (speedup 1.0000x reference)
#include <cuda_runtime.h>
#include <cuda_bf16.h>
#include <math.h>
#include <stdint.h>

#define NSZ 512
#define DSZ 128
#define NN  (NSZ*NSZ)   // 262144

// Scratch. a/b in split-bf16, d-major K-contiguous: A[d][i][k], B[d][j][k]
__device__ uint16_t g_Ah[(size_t)DSZ * NN];
__device__ uint16_t g_Al[(size_t)DSZ * NN];
__device__ uint16_t g_Bh[(size_t)DSZ * NN];
__device__ uint16_t g_Bl[(size_t)DSZ * NN];
__device__ float    g_X [(size_t)DSZ * NN];   // X[d][i][j] fp32

// Pre-split weights (hi/lo bf16)
__device__ uint16_t g_Wph[256*128], g_Wpl[256*128];   // w_ab_p
__device__ uint16_t g_Wgh[256*128], g_Wgl[256*128];   // w_ab_g
__device__ uint16_t g_W3zh[128*128], g_W3zl[128*128]; // w_z
__device__ uint16_t g_W3gh[128*128], g_W3gl[128*128]; // w_g

// ---------------------------------------------------------------------------
// helpers
// ---------------------------------------------------------------------------
__device__ __forceinline__ uint32_t smem_u32(const void* p) {
    uint32_t a;
    asm("{ .reg .u64 t; cvta.to.shared.u64 t, %1; cvt.u32.u64 %0, t; }"
        : "=r"(a) : "l"(p));
    return a;
}
__device__ __forceinline__ void ldsm_x4(uint32_t* r, uint32_t addr) {
    asm volatile("ldmatrix.sync.aligned.m8n8.x4.shared.b16 {%0,%1,%2,%3}, [%4];"
        : "=r"(r[0]), "=r"(r[1]), "=r"(r[2]), "=r"(r[3]) : "r"(addr));
}
__device__ __forceinline__ void ldsm_x2(uint32_t* r, uint32_t addr) {
    asm volatile("ldmatrix.sync.aligned.m8n8.x2.shared.b16 {%0,%1}, [%2];"
        : "=r"(r[0]), "=r"(r[1]) : "r"(addr));
}
__device__ __forceinline__ void mma_bf16(float* d, const uint32_t* a, const uint32_t* b) {
    asm volatile("mma.sync.aligned.m16n8k16.row.col.f32.bf16.bf16.f32 "
        "{%0,%1,%2,%3}, {%4,%5,%6,%7}, {%8,%9}, {%0,%1,%2,%3};"
        : "+f"(d[0]), "+f"(d[1]), "+f"(d[2]), "+f"(d[3])
        : "r"(a[0]), "r"(a[1]), "r"(a[2]), "r"(a[3]), "r"(b[0]), "r"(b[1]));
}
__device__ __forceinline__ void cp16(uint32_t dst, const void* src) {
    asm volatile("cp.async.cg.shared.global [%0], [%1], 16;" :: "r"(dst), "l"(src));
}
#define CP_COMMIT() asm volatile("cp.async.commit_group;")
#define CP_WAIT0()  asm volatile("cp.async.wait_group 0;")
#define CP_WAIT1()  asm volatile("cp.async.wait_group 1;")

// padded-row (272B) ldmatrix addressing for K=128 bf16 tiles
#define PRB 272
__device__ __forceinline__ uint32_t addrA(uint32_t base, int m, int k, int lane) {
    int g = lane >> 3;
    int row = m + ((g & 1) << 3) + (lane & 7);
    int col = k + ((g & 2) << 2);
    return base + row*PRB + col*2;
}
__device__ __forceinline__ uint32_t addrB(uint32_t base, int n, int k, int lane) {
    int g = (lane >> 3) & 1;
    int row = n + (lane & 7);
    int col = k + (g << 3);
    return base + row*PRB + col*2;
}
#define MATPB (128*PRB)   // 34816 B per 128-row matrix tile

// ---------------------------------------------------------------------------
// Kernel 0: split weights into bf16 hi/lo
// ---------------------------------------------------------------------------
__global__ void __launch_bounds__(256) prep_w(
    const float* __restrict__ wp, const float* __restrict__ wg,
    const float* __restrict__ w3g, const float* __restrict__ w3z)
{
    int idx = blockIdx.x * 256 + threadIdx.x;   // 0..98303
    float v; uint16_t* dh; uint16_t* dl; int off;
    if (idx < 32768)       { v = wp[idx];          dh = g_Wph;  dl = g_Wpl;  off = idx; }
    else if (idx < 65536)  { v = wg[idx-32768];    dh = g_Wgh;  dl = g_Wgl;  off = idx-32768; }
    else if (idx < 81920)  { v = w3g[idx-65536];   dh = g_W3gh; dl = g_W3gl; off = idx-65536; }
    else                   { v = w3z[idx-81920];   dh = g_W3zh; dl = g_W3zl; off = idx-81920; }
    __nv_bfloat16 h = __float2bfloat16(v);
    float lo = v - __bfloat162float(h);
    dh[off] = __bfloat16_as_ushort(h);
    dl[off] = __bfloat16_as_ushort(__float2bfloat16(lo));
}

// ---------------------------------------------------------------------------
// Kernel 1 (HMMA): LN(z) -> dual projection -> sigmoid gate -> mask -> split
// CTA: 128 pixels x 128 channels. grid (2048, 2). 256 thr.
// smem: W[4 mats]=139264 | ZH=34816 | ZL=34816 | mask 512 | bp 512 | bg 512
// ---------------------------------------------------------------------------
#define K1_W0   0
#define K1_ZH   139264
#define K1_ZL   174080
#define K1_MSK  208896
#define K1_BP   209408
#define K1_BG   209920
#define K1_SMEM 210432

__global__ void __launch_bounds__(256, 1) k1_mma(
    const float* __restrict__ z, const float* __restrict__ mask,
    const float* __restrict__ b_ab_p, const float* __restrict__ b_ab_g,
    const float* __restrict__ ln_g, const float* __restrict__ ln_b)
{
    extern __shared__ char smc[];
    const uint32_t sb = smem_u32(smc);
    const int tid = threadIdx.x, wid = tid >> 5, lane = tid & 31;
    const int r0 = blockIdx.x * 128;
    const int c0 = blockIdx.y * 128;

    float* zf = (float*)smc;   // overlay on W region: 128 x 132 fp32

    for (int i = tid; i < 128*128; i += 256) {
        int r = i >> 7, c = i & 127;
        zf[r*132 + c] = z[(size_t)(r0 + r)*128 + c];
    }
    if (tid < 128) {
        ((float*)(smc + K1_MSK))[tid] = mask[r0 + tid];
        ((float*)(smc + K1_BP))[tid]  = b_ab_p[c0 + tid];
        ((float*)(smc + K1_BG))[tid]  = b_ab_g[c0 + tid];
    }
    __syncthreads();

    // LN rows -> ZH/ZL bf16
    for (int row = wid; row < 128; row += 8) {
        float s = 0.f, s2 = 0.f;
        #pragma unroll
        for (int c = lane; c < 128; c += 32) {
            float v = zf[row*132 + c];
            s += v; s2 += v*v;
        }
        #pragma unroll
        for (int o = 16; o > 0; o >>= 1) {
            s  += __shfl_xor_sync(0xffffffffu, s, o);
            s2 += __shfl_xor_sync(0xffffffffu, s2, o);
        }
        float mu = s * (1.f/128.f);
        float var = s2 * (1.f/128.f) - mu*mu;
        float rs = rsqrtf(var + 1e-5f);
        #pragma unroll
        for (int c = lane; c < 128; c += 32) {
            float v = (zf[row*132 + c] - mu) * rs * __ldg(&ln_g[c]) + __ldg(&ln_b[c]);
            __nv_bfloat16 h = __float2bfloat16(v);
            float lo = v - __bfloat162float(h);
            *(uint16_t*)(smc + K1_ZH + row*PRB + c*2) = __bfloat16_as_ushort(h);
            *(uint16_t*)(smc + K1_ZL + row*PRB + c*2) = __bfloat16_as_ushort(__float2bfloat16(lo));
        }
    }
    __syncthreads();   // zf (W overlay) dead

    // cp.async weights: [phi, plo, ghi, glo] rows c0..c0+127
    const uint16_t* __restrict__ wsrc[4] = {
        g_Wph + (size_t)c0*128, g_Wpl + (size_t)c0*128,
        g_Wgh + (size_t)c0*128, g_Wgl + (size_t)c0*128 };
    for (int i = tid; i < 8192; i += 256) {
        int mat = i >> 11, rem = i & 2047, row = rem >> 4, ch = rem & 15;
        cp16(sb + K1_W0 + mat*MATPB + row*PRB + ch*16, wsrc[mat] + row*128 + ch*8);
    }
    CP_COMMIT(); CP_WAIT0();
    __syncthreads();

    // MMA: warp tile 64x32 (2x4 warp grid)
    const int wm = (wid & 1) * 64, wn = (wid >> 1) * 32;
    float accp[4][4][4], accg[4][4][4];
    #pragma unroll
    for (int a = 0; a < 4; a++)
        #pragma unroll
        for (int b = 0; b < 4; b++)
            #pragma unroll
            for (int cc = 0; cc < 4; cc++) { accp[a][b][cc] = 0.f; accg[a][b][cc] = 0.f; }

    #pragma unroll
    for (int ks = 0; ks < 8; ks++) {
        const int kb = ks * 16;
        uint32_t zh[4][4], bph[4][2], bgh[4][2];
        #pragma unroll
        for (int mf = 0; mf < 4; mf++)
            ldsm_x4(zh[mf], addrA(sb + K1_ZH, wm + mf*16, kb, lane));
        #pragma unroll
        for (int nf = 0; nf < 4; nf++) {
            ldsm_x2(bph[nf], addrB(sb + K1_W0 + 0*MATPB, wn + nf*8, kb, lane));
            ldsm_x2(bgh[nf], addrB(sb + K1_W0 + 2*MATPB, wn + nf*8, kb, lane));
        }
        #pragma unroll
        for (int mf = 0; mf < 4; mf++)
            #pragma unroll
            for (int nf = 0; nf < 4; nf++) {
                mma_bf16(accp[mf][nf], zh[mf], bph[nf]);
                mma_bf16(accg[mf][nf], zh[mf], bgh[nf]);
            }
        {
            uint32_t bpl[4][2], bgl[4][2];
            #pragma unroll
            for (int nf = 0; nf < 4; nf++) {
                ldsm_x2(bpl[nf], addrB(sb + K1_W0 + 1*MATPB, wn + nf*8, kb, lane));
                ldsm_x2(bgl[nf], addrB(sb + K1_W0 + 3*MATPB, wn + nf*8, kb, lane));
            }
            #pragma unroll
            for (int mf = 0; mf < 4; mf++)
                #pragma unroll
                for (int nf = 0; nf < 4; nf++) {
                    mma_bf16(accp[mf][nf], zh[mf], bpl[nf]);
                    mma_bf16(accg[mf][nf], zh[mf], bgl[nf]);
                }
        }
        {
            uint32_t zl[4][4];
            #pragma unroll
            for (int mf = 0; mf < 4; mf++)
                ldsm_x4(zl[mf], addrA(sb + K1_ZL, wm + mf*16, kb, lane));
            #pragma unroll
            for (int mf = 0; mf < 4; mf++)
                #pragma unroll
                for (int nf = 0; nf < 4; nf++) {
                    mma_bf16(accp[mf][nf], zl[mf], bph[nf]);
                    mma_bf16(accg[mf][nf], zl[mf], bgh[nf]);
                }
        }
    }
    __syncthreads();   // ZH/ZL dead -> reuse as stage

    // epilogue: val = (p + bp)*mask*sigmoid(g + bg), staged transposed [col][row]
    float* st  = (float*)(smc + K1_ZH);   // 128 cols x 130 stride
    float* msk = (float*)(smc + K1_MSK);
    float* bpv = (float*)(smc + K1_BP);
    float* bgv = (float*)(smc + K1_BG);
    const int r = lane >> 2, cq = (lane & 3)*2;
    #pragma unroll
    for (int mf = 0; mf < 4; mf++) {
        #pragma unroll
        for (int nf = 0; nf < 4; nf++) {
            #pragma unroll
            for (int half = 0; half < 2; half++) {
                int row = wm + mf*16 + r + half*8;
                float m = msk[row];
                #pragma unroll
                for (int q = 0; q < 2; q++) {
                    int col = wn + nf*8 + cq + q;
                    float p = accp[mf][nf][half*2 + q] + bpv[col];
                    float g = accg[mf][nf][half*2 + q] + bgv[col];
                    st[col*130 + row] = p * m * (1.f/(1.f + expf(-g)));
                }
            }
        }
    }
    __syncthreads();

    uint16_t* dh = (c0 == 0) ? g_Ah : g_Bh;
    uint16_t* dl = (c0 == 0) ? g_Al : g_Bl;
    for (int i = tid; i < 8192; i += 256) {
        int col = i >> 6, rc = i & 63;
        float v0 = st[col*130 + rc*2];
        float v1 = st[col*130 + rc*2 + 1];
        __nv_bfloat16 h0 = __float2bfloat16(v0);
        __nv_bfloat16 h1 = __float2bfloat16(v1);
        float l0 = v0 - __bfloat162float(h0);
        float l1 = v1 - __bfloat162float(h1);
        uint32_t ph = (uint32_t)__bfloat16_as_ushort(h0) |
                      ((uint32_t)__bfloat16_as_ushort(h1) << 16);
        uint32_t pl = (uint32_t)__bfloat16_as_ushort(__float2bfloat16(l0)) |
                      ((uint32_t)__bfloat16_as_ushort(__float2bfloat16(l1)) << 16);
        size_t off = (size_t)col*NN + r0 + rc*2;
        *(uint32_t*)&dh[off] = ph;
        *(uint32_t*)&dl[off] = pl;
    }
}

// ---------------------------------------------------------------------------
// Kernel 2 (HMMA): x[d][i][j] = sum_k A[d][i][k]*B[d][j][k]  (unchanged, passing)
// ---------------------------------------------------------------------------
#define KCH   32
#define ROWB  80
#define MATB  (128*ROWB)
#define BUFB  (4*MATB)
#define K2_SMEM (2*BUFB)

__device__ __forceinline__ uint32_t a2_addr(uint32_t matbase, int m, int k, int lane) {
    int g = lane >> 3;
    int row = m + ((g & 1) << 3) + (lane & 7);
    int col = k + ((g & 2) << 2);
    return matbase + row*ROWB + col*2;
}
__device__ __forceinline__ uint32_t b2_addr(uint32_t matbase, int n, int k, int lane) {
    int g = (lane >> 3) & 1;
    int row = n + (lane & 7);
    int col = k + (g << 3);
    return matbase + row*ROWB + col*2;
}

__global__ void __launch_bounds__(256, 2) k2_einsum_mma()
{
    extern __shared__ char smc[];
    const uint32_t sbase = smem_u32(smc);
    const int tid  = threadIdx.x;
    const int wid  = tid >> 5, lane = tid & 31;
    const int d  = blockIdx.z;
    const int i0 = blockIdx.y * 128;
    const int j0 = blockIdx.x * 128;
    const int wm = (wid & 1) * 64;
    const int wn = (wid >> 1) * 32;

    const uint16_t* __restrict__ srcs[4] = {
        g_Ah + (size_t)d*NN, g_Al + (size_t)d*NN,
        g_Bh + (size_t)d*NN, g_Bl + (size_t)d*NN };

    auto issue = [&](int c) {
        const uint32_t bb = sbase + (c & 1)*BUFB;
        const int k0 = c * KCH;
        #pragma unroll
        for (int i = 0; i < 8; i++) {
            int idx = tid + i*256;
            int mat = idx >> 9;
            int rem = idx & 511;
            int row = rem >> 2;
            int q   = rem & 3;
            int rbase = (mat < 2) ? i0 : j0;
            const uint16_t* s = srcs[mat] + (size_t)(rbase + row)*512 + k0 + q*8;
            cp16(bb + mat*MATB + row*ROWB + q*16, s);
        }
        CP_COMMIT();
    };

    float acc[4][4][4];
    #pragma unroll
    for (int a = 0; a < 4; a++)
        #pragma unroll
        for (int b = 0; b < 4; b++)
            #pragma unroll
            for (int cc = 0; cc < 4; cc++) acc[a][b][cc] = 0.f;

    issue(0);
    for (int c = 0; c < 16; c++) {
        if (c + 1 < 16) { issue(c + 1); CP_WAIT1(); }
        else            { CP_WAIT0(); }
        __syncthreads();

        const uint32_t bb = sbase + (c & 1)*BUFB;
        #pragma unroll
        for (int kk = 0; kk < 2; kk++) {
            const int kb = kk * 16;
            uint32_t af[4][4], bh[4][2], bl[4][2];
            #pragma unroll
            for (int mf = 0; mf < 4; mf++)
                ldsm_x4(af[mf], a2_addr(bb + 0*MATB, wm + mf*16, kb, lane));
            #pragma unroll
            for (int nf = 0; nf < 4; nf++) {
                ldsm_x2(bh[nf], b2_addr(bb + 2*MATB, wn + nf*8, kb, lane));
                ldsm_x2(bl[nf], b2_addr(bb + 3*MATB, wn + nf*8, kb, lane));
            }
            #pragma unroll
            for (int mf = 0; mf < 4; mf++)
                #pragma unroll
                for (int nf = 0; nf < 4; nf++)
                    mma_bf16(acc[mf][nf], af[mf], bh[nf]);
            #pragma unroll
            for (int mf = 0; mf < 4; mf++)
                #pragma unroll
                for (int nf = 0; nf < 4; nf++)
                    mma_bf16(acc[mf][nf], af[mf], bl[nf]);
            #pragma unroll
            for (int mf = 0; mf < 4; mf++)
                ldsm_x4(af[mf], a2_addr(bb + 1*MATB, wm + mf*16, kb, lane));
            #pragma unroll
            for (int mf = 0; mf < 4; mf++)
                #pragma unroll
                for (int nf = 0; nf < 4; nf++)
                    mma_bf16(acc[mf][nf], af[mf], bh[nf]);
        }
        __syncthreads();
    }

    float* __restrict__ X = g_X + (size_t)d * NN;
    const int r  = lane >> 2;
    const int cq = (lane & 3) * 2;
    #pragma unroll
    for (int mf = 0; mf < 4; mf++) {
        #pragma unroll
        for (int nf = 0; nf < 4; nf++) {
            size_t row0 = (size_t)(i0 + wm + mf*16 + r);
            int col = j0 + wn + nf*8 + cq;
            *(float2*)&X[row0*512 + col]       = make_float2(acc[mf][nf][0], acc[mf][nf][1]);
            *(float2*)&X[(row0 + 8)*512 + col] = make_float2(acc[mf][nf][2], acc[mf][nf][3]);
        }
    }
}

// ---------------------------------------------------------------------------
// Kernel 3 (HMMA): out = sigmoid(z·w_g^T + b_g) * (LN(x)·w_z^T + b_z)
// CTA: 64 pixels x 128 channels. grid (4096). 256 thr.
// smem: W[4]=139264 | XH 17408 | XL 17408 | ZH 17408 | ZL 17408 | bz 512 | bg 512
// ---------------------------------------------------------------------------
#define K3_W0  0
#define K3_XH  139264
#define K3_XL  156672
#define K3_ZH  174080
#define K3_ZL  191488
#define K3_BZ  208896
#define K3_BG  209408
#define K3_SMEM 209920

__global__ void __launch_bounds__(256, 1) k3_mma(
    const float* __restrict__ z,
    const float* __restrict__ b_g, const float* __restrict__ b_z,
    const float* __restrict__ ln_g, const float* __restrict__ ln_b,
    float* __restrict__ out)
{
    extern __shared__ char smc[];
    const uint32_t sb = smem_u32(smc);
    const int tid = threadIdx.x, wid = tid >> 5, lane = tid & 31;
    const int q0 = blockIdx.x * 64;

    float* xf = (float*)smc;             // 64 x 133 overlay on W
    float* zf = (float*)(smc + 34816);   // 64 x 133 overlay on W

    for (int i = tid; i < 64*128; i += 256) {
        int dd = i >> 6, ql = i & 63;
        xf[ql*133 + dd] = g_X[(size_t)dd*NN + q0 + ql];
    }
    for (int i = tid; i < 64*128; i += 256) {
        int r = i >> 7, c = i & 127;
        zf[r*133 + c] = z[(size_t)(q0 + r)*128 + c];
    }
    if (tid < 128) {
        ((float*)(smc + K3_BZ))[tid] = b_z[tid];
        ((float*)(smc + K3_BG))[tid] = b_g[tid];
    }
    __syncthreads();

    // LN(x) rows -> XH/XL
    for (int row = wid; row < 64; row += 8) {
        float s = 0.f, s2 = 0.f;
        #pragma unroll
        for (int c = lane; c < 128; c += 32) {
            float v = xf[row*133 + c];
            s += v; s2 += v*v;
        }
        #pragma unroll
        for (int o = 16; o > 0; o >>= 1) {
            s  += __shfl_xor_sync(0xffffffffu, s, o);
            s2 += __shfl_xor_sync(0xffffffffu, s2, o);
        }
        float mu = s * (1.f/128.f);
        float var = s2 * (1.f/128.f) - mu*mu;
        float rs = rsqrtf(var + 1e-5f);
        #pragma unroll
        for (int c = lane; c < 128; c += 32) {
            float v = (xf[row*133 + c] - mu) * rs * __ldg(&ln_g[c]) + __ldg(&ln_b[c]);
            __nv_bfloat16 h = __float2bfloat16(v);
            float lo = v - __bfloat162float(h);
            *(uint16_t*)(smc + K3_XH + row*PRB + c*2) = __bfloat16_as_ushort(h);
            *(uint16_t*)(smc + K3_XL + row*PRB + c*2) = __bfloat16_as_ushort(__float2bfloat16(lo));
        }
    }
    // raw z -> ZH/ZL
    for (int i = tid; i < 64*128; i += 256) {
        int r = i >> 7, c = i & 127;
        float v = zf[r*133 + c];
        __nv_bfloat16 h = __float2bfloat16(v);
        float lo = v - __bfloat162float(h);
        *(uint16_t*)(smc + K3_ZH + r*PRB + c*2) = __bfloat16_as_ushort(h);
        *(uint16_t*)(smc + K3_ZL + r*PRB + c*2) = __bfloat16_as_ushort(__float2bfloat16(lo));
    }
    __syncthreads();   // overlays dead

    // cp.async weights: [wzh, wzl, wgh, wgl]
    const uint16_t* __restrict__ wsrc[4] = { g_W3zh, g_W3zl, g_W3gh, g_W3gl };
    for (int i = tid; i < 8192; i += 256) {
        int mat = i >> 11, rem = i & 2047, row = rem >> 4, ch = rem & 15;
        cp16(sb + K3_W0 + mat*MATPB + row*PRB + ch*16, wsrc[mat] + row*128 + ch*8);
    }
    CP_COMMIT(); CP_WAIT0();
    __syncthreads();

    // MMA: warp tile 32x32 (2x4 warp grid over 64x128)
    const int wm = (wid & 1) * 32, wn = (wid >> 1) * 32;
    float accx[2][4][4], accg[2][4][4];
    #pragma unroll
    for (int a = 0; a < 2; a++)
        #pragma unroll
        for (int b = 0; b < 4; b++)
            #pragma unroll
            for (int cc = 0; cc < 4; cc++) { accx[a][b][cc] = 0.f; accg[a][b][cc] = 0.f; }

    #pragma unroll
    for (int ks = 0; ks < 8; ks++) {
        const int kb = ks * 16;
        uint32_t xh[2][4], zh[2][4], bzh[4][2], bgh[4][2];
        #pragma unroll
        for (int mf = 0; mf < 2; mf++) {
            ldsm_x4(xh[mf], addrA(sb + K3_XH, wm + mf*16, kb, lane));
            ldsm_x4(zh[mf], addrA(sb + K3_ZH, wm + mf*16, kb, lane));
        }
        #pragma unroll
        for (int nf = 0; nf < 4; nf++) {
            ldsm_x2(bzh[nf], addrB(sb + K3_W0 + 0*MATPB, wn + nf*8, kb, lane));
            ldsm_x2(bgh[nf], addrB(sb + K3_W0 + 2*MATPB, wn + nf*8, kb, lane));
        }
        #pragma unroll
        for (int mf = 0; mf < 2; mf++)
            #pragma unroll
            for (int nf = 0; nf < 4; nf++) {
                mma_bf16(accx[mf][nf], xh[mf], bzh[nf]);
                mma_bf16(accg[mf][nf], zh[mf], bgh[nf]);
            }
        {
            uint32_t bzl[4][2], bgl[4][2];
            #pragma unroll
            for (int nf = 0; nf < 4; nf++) {
                ldsm_x2(bzl[nf], addrB(sb + K3_W0 + 1*MATPB, wn + nf*8, kb, lane));
                ldsm_x2(bgl[nf], addrB(sb + K3_W0 + 3*MATPB, wn + nf*8, kb, lane));
            }
            #pragma unroll
            for (int mf = 0; mf < 2; mf++)
                #pragma unroll
                for (int nf = 0; nf < 4; nf++) {
                    mma_bf16(accx[mf][nf], xh[mf], bzl[nf]);
                    mma_bf16(accg[mf][nf], zh[mf], bgl[nf]);
                }
        }
        {
            uint32_t xl[2][4], zl[2][4];
            #pragma unroll
            for (int mf = 0; mf < 2; mf++) {
                ldsm_x4(xl[mf], addrA(sb + K3_XL, wm + mf*16, kb, lane));
                ldsm_x4(zl[mf], addrA(sb + K3_ZL, wm + mf*16, kb, lane));
            }
            #pragma unroll
            for (int mf = 0; mf < 2; mf++)
                #pragma unroll
                for (int nf = 0; nf < 4; nf++) {
                    mma_bf16(accx[mf][nf], xl[mf], bzh[nf]);
                    mma_bf16(accg[mf][nf], zl[mf], bgh[nf]);
                }
        }
    }

    // epilogue: direct stores
    float* bzv = (float*)(smc + K3_BZ);
    float* bgv = (float*)(smc + K3_BG);
    const int r = lane >> 2, cq = (lane & 3)*2;
    #pragma unroll
    for (int mf = 0; mf < 2; mf++) {
        #pragma unroll
        for (int nf = 0; nf < 4; nf++) {
            #pragma unroll
            for (int half = 0; half < 2; half++) {
                int qrow = q0 + wm + mf*16 + r + half*8;
                int col = wn + nf*8 + cq;
                float g0 = 1.f/(1.f + expf(-(accg[mf][nf][half*2+0] + bgv[col])));
                float g1 = 1.f/(1.f + expf(-(accg[mf][nf][half*2+1] + bgv[col+1])));
                float v0 = g0 * (accx[mf][nf][half*2+0] + bzv[col]);
                float v1 = g1 * (accx[mf][nf][half*2+1] + bzv[col+1]);
                *(float2*)&out[(size_t)qrow*128 + col] = make_float2(v0, v1);
            }
        }
    }
}

// ---------------------------------------------------------------------------
extern "C" void kernel_launch(void* const* d_in, const int* in_sizes, int n_in,
                              void* d_out, int out_size)
{
    const float* z        = (const float*)d_in[0];
    const float* mask     = (const float*)d_in[1];
    const float* w_ab_p   = (const float*)d_in[2];
    const float* b_ab_p   = (const float*)d_in[3];
    const float* w_ab_g   = (const float*)d_in[4];
    const float* b_ab_g   = (const float*)d_in[5];
    const float* w_g      = (const float*)d_in[6];
    const float* b_g      = (const float*)d_in[7];
    const float* w_z      = (const float*)d_in[8];
    const float* b_z      = (const float*)d_in[9];
    const float* ln_in_g  = (const float*)d_in[10];
    const float* ln_in_b  = (const float*)d_in[11];
    const float* ln_out_g = (const float*)d_in[12];
    const float* ln_out_b = (const float*)d_in[13];
    float* out = (float*)d_out;

    cudaFuncSetAttribute(k1_mma,        cudaFuncAttributeMaxDynamicSharedMemorySize, K1_SMEM);
    cudaFuncSetAttribute(k2_einsum_mma, cudaFuncAttributeMaxDynamicSharedMemorySize, K2_SMEM);
    cudaFuncSetAttribute(k3_mma,        cudaFuncAttributeMaxDynamicSharedMemorySize, K3_SMEM);

    prep_w<<<384, 256>>>(w_ab_p, w_ab_g, w_g, w_z);
    k1_mma<<<dim3(2048, 2), 256, K1_SMEM>>>(z, mask, b_ab_p, b_ab_g, ln_in_g, ln_in_b);
    k2_einsum_mma<<<dim3(4, 4, 128), 256, K2_SMEM>>>();
    k3_mma<<<4096, 256, K3_SMEM>>>(z, b_g, b_z, ln_out_g, ln_out_b, out);
}

// round 10
// speedup vs baseline: 1.0003x; 1.0003x over previous
#include <cuda_runtime.h>
#include <cuda_bf16.h>
#include <math.h>
#include <stdint.h>

#define NSZ 512
#define DSZ 128
#define NN  (NSZ*NSZ)   // 262144

// Scratch. a/b in split-bf16, d-major K-contiguous: A[d][i][k], B[d][j][k]
__device__ uint16_t g_Ah[(size_t)DSZ * NN];
__device__ uint16_t g_Al[(size_t)DSZ * NN];
__device__ uint16_t g_Bh[(size_t)DSZ * NN];
__device__ uint16_t g_Bl[(size_t)DSZ * NN];
__device__ float    g_X [(size_t)DSZ * NN];   // X[d][i][j] fp32

// Pre-split weights (hi/lo bf16)
__device__ uint16_t g_Wph[256*128], g_Wpl[256*128];   // w_ab_p
__device__ uint16_t g_Wgh[256*128], g_Wgl[256*128];   // w_ab_g
__device__ uint16_t g_W3zh[128*128], g_W3zl[128*128]; // w_z
__device__ uint16_t g_W3gh[128*128], g_W3gl[128*128]; // w_g

// ---------------------------------------------------------------------------
// helpers
// ---------------------------------------------------------------------------
__device__ __forceinline__ uint32_t smem_u32(const void* p) {
    uint32_t a;
    asm("{ .reg .u64 t; cvta.to.shared.u64 t, %1; cvt.u32.u64 %0, t; }"
        : "=r"(a) : "l"(p));
    return a;
}
__device__ __forceinline__ void ldsm_x4(uint32_t* r, uint32_t addr) {
    asm volatile("ldmatrix.sync.aligned.m8n8.x4.shared.b16 {%0,%1,%2,%3}, [%4];"
        : "=r"(r[0]), "=r"(r[1]), "=r"(r[2]), "=r"(r[3]) : "r"(addr));
}
__device__ __forceinline__ void ldsm_x2(uint32_t* r, uint32_t addr) {
    asm volatile("ldmatrix.sync.aligned.m8n8.x2.shared.b16 {%0,%1}, [%2];"
        : "=r"(r[0]), "=r"(r[1]) : "r"(addr));
}
__device__ __forceinline__ void mma_bf16(float* d, const uint32_t* a, const uint32_t* b) {
    asm volatile("mma.sync.aligned.m16n8k16.row.col.f32.bf16.bf16.f32 "
        "{%0,%1,%2,%3}, {%4,%5,%6,%7}, {%8,%9}, {%0,%1,%2,%3};"
        : "+f"(d[0]), "+f"(d[1]), "+f"(d[2]), "+f"(d[3])
        : "r"(a[0]), "r"(a[1]), "r"(a[2]), "r"(a[3]), "r"(b[0]), "r"(b[1]));
}
__device__ __forceinline__ void cp16(uint32_t dst, const void* src) {
    asm volatile("cp.async.cg.shared.global [%0], [%1], 16;" :: "r"(dst), "l"(src));
}
#define CP_COMMIT() asm volatile("cp.async.commit_group;")
#define CP_WAIT0()  asm volatile("cp.async.wait_group 0;")
#define CP_WAIT1()  asm volatile("cp.async.wait_group 1;")

// padded-row (272B) ldmatrix addressing for K=128 bf16 tiles
#define PRB 272
__device__ __forceinline__ uint32_t addrA(uint32_t base, int m, int k, int lane) {
    int g = lane >> 3;
    int row = m + ((g & 1) << 3) + (lane & 7);
    int col = k + ((g & 2) << 2);
    return base + row*PRB + col*2;
}
__device__ __forceinline__ uint32_t addrB(uint32_t base, int n, int k, int lane) {
    int g = (lane >> 3) & 1;
    int row = n + (lane & 7);
    int col = k + (g << 3);
    return base + row*PRB + col*2;
}
#define MATPB (128*PRB)   // 34816 B per 128-row matrix tile

// ---------------------------------------------------------------------------
// Kernel 0: split weights into bf16 hi/lo
// ---------------------------------------------------------------------------
__global__ void __launch_bounds__(256) prep_w(
    const float* __restrict__ wp, const float* __restrict__ wg,
    const float* __restrict__ w3g, const float* __restrict__ w3z)
{
    int idx = blockIdx.x * 256 + threadIdx.x;   // 0..98303
    float v; uint16_t* dh; uint16_t* dl; int off;
    if (idx < 32768)       { v = wp[idx];          dh = g_Wph;  dl = g_Wpl;  off = idx; }
    else if (idx < 65536)  { v = wg[idx-32768];    dh = g_Wgh;  dl = g_Wgl;  off = idx-32768; }
    else if (idx < 81920)  { v = w3g[idx-65536];   dh = g_W3gh; dl = g_W3gl; off = idx-65536; }
    else                   { v = w3z[idx-81920];   dh = g_W3zh; dl = g_W3zl; off = idx-81920; }
    __nv_bfloat16 h = __float2bfloat16(v);
    float lo = v - __bfloat162float(h);
    dh[off] = __bfloat16_as_ushort(h);
    dl[off] = __bfloat16_as_ushort(__float2bfloat16(lo));
}

// ---------------------------------------------------------------------------
// Kernel 1 (HMMA): LN(z) -> dual projection -> sigmoid gate -> mask -> split
// CTA: 128 pixels x 128 channels. grid (2048, 2). 256 thr.
// smem: W[4 mats]=139264 | ZH=34816 | ZL=34816 | mask 512 | bp 512 | bg 512
// ---------------------------------------------------------------------------
#define K1_W0   0
#define K1_ZH   139264
#define K1_ZL   174080
#define K1_MSK  208896
#define K1_BP   209408
#define K1_BG   209920
#define K1_SMEM 210432

__global__ void __launch_bounds__(256, 1) k1_mma(
    const float* __restrict__ z, const float* __restrict__ mask,
    const float* __restrict__ b_ab_p, const float* __restrict__ b_ab_g,
    const float* __restrict__ ln_g, const float* __restrict__ ln_b)
{
    extern __shared__ char smc[];
    const uint32_t sb = smem_u32(smc);
    const int tid = threadIdx.x, wid = tid >> 5, lane = tid & 31;
    const int r0 = blockIdx.x * 128;
    const int c0 = blockIdx.y * 128;

    float* zf = (float*)smc;   // overlay on W region: 128 x 132 fp32

    for (int i = tid; i < 128*128; i += 256) {
        int r = i >> 7, c = i & 127;
        zf[r*132 + c] = z[(size_t)(r0 + r)*128 + c];
    }
    if (tid < 128) {
        ((float*)(smc + K1_MSK))[tid] = mask[r0 + tid];
        ((float*)(smc + K1_BP))[tid]  = b_ab_p[c0 + tid];
        ((float*)(smc + K1_BG))[tid]  = b_ab_g[c0 + tid];
    }
    __syncthreads();

    // LN rows -> ZH/ZL bf16
    for (int row = wid; row < 128; row += 8) {
        float s = 0.f, s2 = 0.f;
        #pragma unroll
        for (int c = lane; c < 128; c += 32) {
            float v = zf[row*132 + c];
            s += v; s2 += v*v;
        }
        #pragma unroll
        for (int o = 16; o > 0; o >>= 1) {
            s  += __shfl_xor_sync(0xffffffffu, s, o);
            s2 += __shfl_xor_sync(0xffffffffu, s2, o);
        }
        float mu = s * (1.f/128.f);
        float var = s2 * (1.f/128.f) - mu*mu;
        float rs = rsqrtf(var + 1e-5f);
        #pragma unroll
        for (int c = lane; c < 128; c += 32) {
            float v = (zf[row*132 + c] - mu) * rs * __ldg(&ln_g[c]) + __ldg(&ln_b[c]);
            __nv_bfloat16 h = __float2bfloat16(v);
            float lo = v - __bfloat162float(h);
            *(uint16_t*)(smc + K1_ZH + row*PRB + c*2) = __bfloat16_as_ushort(h);
            *(uint16_t*)(smc + K1_ZL + row*PRB + c*2) = __bfloat16_as_ushort(__float2bfloat16(lo));
        }
    }
    __syncthreads();   // zf (W overlay) dead

    // cp.async weights: [phi, plo, ghi, glo] rows c0..c0+127
    const uint16_t* __restrict__ wsrc[4] = {
        g_Wph + (size_t)c0*128, g_Wpl + (size_t)c0*128,
        g_Wgh + (size_t)c0*128, g_Wgl + (size_t)c0*128 };
    for (int i = tid; i < 8192; i += 256) {
        int mat = i >> 11, rem = i & 2047, row = rem >> 4, ch = rem & 15;
        cp16(sb + K1_W0 + mat*MATPB + row*PRB + ch*16, wsrc[mat] + row*128 + ch*8);
    }
    CP_COMMIT(); CP_WAIT0();
    __syncthreads();

    // MMA: warp tile 64x32 (2x4 warp grid)
    const int wm = (wid & 1) * 64, wn = (wid >> 1) * 32;
    float accp[4][4][4], accg[4][4][4];
    #pragma unroll
    for (int a = 0; a < 4; a++)
        #pragma unroll
        for (int b = 0; b < 4; b++)
            #pragma unroll
            for (int cc = 0; cc < 4; cc++) { accp[a][b][cc] = 0.f; accg[a][b][cc] = 0.f; }

    #pragma unroll
    for (int ks = 0; ks < 8; ks++) {
        const int kb = ks * 16;
        uint32_t zh[4][4], bph[4][2], bgh[4][2];
        #pragma unroll
        for (int mf = 0; mf < 4; mf++)
            ldsm_x4(zh[mf], addrA(sb + K1_ZH, wm + mf*16, kb, lane));
        #pragma unroll
        for (int nf = 0; nf < 4; nf++) {
            ldsm_x2(bph[nf], addrB(sb + K1_W0 + 0*MATPB, wn + nf*8, kb, lane));
            ldsm_x2(bgh[nf], addrB(sb + K1_W0 + 2*MATPB, wn + nf*8, kb, lane));
        }
        #pragma unroll
        for (int mf = 0; mf < 4; mf++)
            #pragma unroll
            for (int nf = 0; nf < 4; nf++) {
                mma_bf16(accp[mf][nf], zh[mf], bph[nf]);
                mma_bf16(accg[mf][nf], zh[mf], bgh[nf]);
            }
        {
            uint32_t bpl[4][2], bgl[4][2];
            #pragma unroll
            for (int nf = 0; nf < 4; nf++) {
                ldsm_x2(bpl[nf], addrB(sb + K1_W0 + 1*MATPB, wn + nf*8, kb, lane));
                ldsm_x2(bgl[nf], addrB(sb + K1_W0 + 3*MATPB, wn + nf*8, kb, lane));
            }
            #pragma unroll
            for (int mf = 0; mf < 4; mf++)
                #pragma unroll
                for (int nf = 0; nf < 4; nf++) {
                    mma_bf16(accp[mf][nf], zh[mf], bpl[nf]);
                    mma_bf16(accg[mf][nf], zh[mf], bgl[nf]);
                }
        }
        {
            uint32_t zl[4][4];
            #pragma unroll
            for (int mf = 0; mf < 4; mf++)
                ldsm_x4(zl[mf], addrA(sb + K1_ZL, wm + mf*16, kb, lane));
            #pragma unroll
            for (int mf = 0; mf < 4; mf++)
                #pragma unroll
                for (int nf = 0; nf < 4; nf++) {
                    mma_bf16(accp[mf][nf], zl[mf], bph[nf]);
                    mma_bf16(accg[mf][nf], zl[mf], bgh[nf]);
                }
        }
    }
    __syncthreads();   // ZH/ZL dead -> reuse as stage

    // epilogue: val = (p + bp)*mask*sigmoid(g + bg), staged transposed [col][row]
    float* st  = (float*)(smc + K1_ZH);   // 128 cols x 130 stride
    float* msk = (float*)(smc + K1_MSK);
    float* bpv = (float*)(smc + K1_BP);
    float* bgv = (float*)(smc + K1_BG);
    const int r = lane >> 2, cq = (lane & 3)*2;
    #pragma unroll
    for (int mf = 0; mf < 4; mf++) {
        #pragma unroll
        for (int nf = 0; nf < 4; nf++) {
            #pragma unroll
            for (int half = 0; half < 2; half++) {
                int row = wm + mf*16 + r + half*8;
                float m = msk[row];
                #pragma unroll
                for (int q = 0; q < 2; q++) {
                    int col = wn + nf*8 + cq + q;
                    float p = accp[mf][nf][half*2 + q] + bpv[col];
                    float g = accg[mf][nf][half*2 + q] + bgv[col];
                    st[col*130 + row] = p * m * (1.f/(1.f + expf(-g)));
                }
            }
        }
    }
    __syncthreads();

    uint16_t* dh = (c0 == 0) ? g_Ah : g_Bh;
    uint16_t* dl = (c0 == 0) ? g_Al : g_Bl;
    for (int i = tid; i < 8192; i += 256) {
        int col = i >> 6, rc = i & 63;
        float v0 = st[col*130 + rc*2];
        float v1 = st[col*130 + rc*2 + 1];
        __nv_bfloat16 h0 = __float2bfloat16(v0);
        __nv_bfloat16 h1 = __float2bfloat16(v1);
        float l0 = v0 - __bfloat162float(h0);
        float l1 = v1 - __bfloat162float(h1);
        uint32_t ph = (uint32_t)__bfloat16_as_ushort(h0) |
                      ((uint32_t)__bfloat16_as_ushort(h1) << 16);
        uint32_t pl = (uint32_t)__bfloat16_as_ushort(__float2bfloat16(l0)) |
                      ((uint32_t)__bfloat16_as_ushort(__float2bfloat16(l1)) << 16);
        size_t off = (size_t)col*NN + r0 + rc*2;
        *(uint32_t*)&dh[off] = ph;
        *(uint32_t*)&dl[off] = pl;
    }
}

// ---------------------------------------------------------------------------
// Kernel 2 (HMMA): x[d][i][j] = sum_k A[d][i][k]*B[d][j][k]  (unchanged, passing)
// ---------------------------------------------------------------------------
#define KCH   32
#define ROWB  80
#define MATB  (128*ROWB)
#define BUFB  (4*MATB)
#define K2_SMEM (2*BUFB)

__device__ __forceinline__ uint32_t a2_addr(uint32_t matbase, int m, int k, int lane) {
    int g = lane >> 3;
    int row = m + ((g & 1) << 3) + (lane & 7);
    int col = k + ((g & 2) << 2);
    return matbase + row*ROWB + col*2;
}
__device__ __forceinline__ uint32_t b2_addr(uint32_t matbase, int n, int k, int lane) {
    int g = (lane >> 3) & 1;
    int row = n + (lane & 7);
    int col = k + (g << 3);
    return matbase + row*ROWB + col*2;
}

__global__ void __launch_bounds__(256, 2) k2_einsum_mma()
{
    extern __shared__ char smc[];
    const uint32_t sbase = smem_u32(smc);
    const int tid  = threadIdx.x;
    const int wid  = tid >> 5, lane = tid & 31;
    const int d  = blockIdx.z;
    const int i0 = blockIdx.y * 128;
    const int j0 = blockIdx.x * 128;
    const int wm = (wid & 1) * 64;
    const int wn = (wid >> 1) * 32;

    const uint16_t* __restrict__ srcs[4] = {
        g_Ah + (size_t)d*NN, g_Al + (size_t)d*NN,
        g_Bh + (size_t)d*NN, g_Bl + (size_t)d*NN };

    auto issue = [&](int c) {
        const uint32_t bb = sbase + (c & 1)*BUFB;
        const int k0 = c * KCH;
        #pragma unroll
        for (int i = 0; i < 8; i++) {
            int idx = tid + i*256;
            int mat = idx >> 9;
            int rem = idx & 511;
            int row = rem >> 2;
            int q   = rem & 3;
            int rbase = (mat < 2) ? i0 : j0;
            const uint16_t* s = srcs[mat] + (size_t)(rbase + row)*512 + k0 + q*8;
            cp16(bb + mat*MATB + row*ROWB + q*16, s);
        }
        CP_COMMIT();
    };

    float acc[4][4][4];
    #pragma unroll
    for (int a = 0; a < 4; a++)
        #pragma unroll
        for (int b = 0; b < 4; b++)
            #pragma unroll
            for (int cc = 0; cc < 4; cc++) acc[a][b][cc] = 0.f;

    issue(0);
    for (int c = 0; c < 16; c++) {
        if (c + 1 < 16) { issue(c + 1); CP_WAIT1(); }
        else            { CP_WAIT0(); }
        __syncthreads();

        const uint32_t bb = sbase + (c & 1)*BUFB;
        #pragma unroll
        for (int kk = 0; kk < 2; kk++) {
            const int kb = kk * 16;
            uint32_t af[4][4], bh[4][2], bl[4][2];
            #pragma unroll
            for (int mf = 0; mf < 4; mf++)
                ldsm_x4(af[mf], a2_addr(bb + 0*MATB, wm + mf*16, kb, lane));
            #pragma unroll
            for (int nf = 0; nf < 4; nf++) {
                ldsm_x2(bh[nf], b2_addr(bb + 2*MATB, wn + nf*8, kb, lane));
                ldsm_x2(bl[nf], b2_addr(bb + 3*MATB, wn + nf*8, kb, lane));
            }
            #pragma unroll
            for (int mf = 0; mf < 4; mf++)
                #pragma unroll
                for (int nf = 0; nf < 4; nf++)
                    mma_bf16(acc[mf][nf], af[mf], bh[nf]);
            #pragma unroll
            for (int mf = 0; mf < 4; mf++)
                #pragma unroll
                for (int nf = 0; nf < 4; nf++)
                    mma_bf16(acc[mf][nf], af[mf], bl[nf]);
            #pragma unroll
            for (int mf = 0; mf < 4; mf++)
                ldsm_x4(af[mf], a2_addr(bb + 1*MATB, wm + mf*16, kb, lane));
            #pragma unroll
            for (int mf = 0; mf < 4; mf++)
                #pragma unroll
                for (int nf = 0; nf < 4; nf++)
                    mma_bf16(acc[mf][nf], af[mf], bh[nf]);
        }
        __syncthreads();
    }

    float* __restrict__ X = g_X + (size_t)d * NN;
    const int r  = lane >> 2;
    const int cq = (lane & 3) * 2;
    #pragma unroll
    for (int mf = 0; mf < 4; mf++) {
        #pragma unroll
        for (int nf = 0; nf < 4; nf++) {
            size_t row0 = (size_t)(i0 + wm + mf*16 + r);
            int col = j0 + wn + nf*8 + cq;
            *(float2*)&X[row0*512 + col]       = make_float2(acc[mf][nf][0], acc[mf][nf][1]);
            *(float2*)&X[(row0 + 8)*512 + col] = make_float2(acc[mf][nf][2], acc[mf][nf][3]);
        }
    }
}

// ---------------------------------------------------------------------------
// Kernel 3 (HMMA): out = sigmoid(z·w_g^T + b_g) * (LN(x)·w_z^T + b_z)
// CTA: 64 pixels x 128 channels. grid (4096). 256 thr.
// smem: W[4]=139264 | XH 17408 | XL 17408 | ZH 17408 | ZL 17408 | bz 512 | bg 512
// ---------------------------------------------------------------------------
#define K3_W0  0
#define K3_XH  139264
#define K3_XL  156672
#define K3_ZH  174080
#define K3_ZL  191488
#define K3_BZ  208896
#define K3_BG  209408
#define K3_SMEM 209920

__global__ void __launch_bounds__(256, 1) k3_mma(
    const float* __restrict__ z,
    const float* __restrict__ b_g, const float* __restrict__ b_z,
    const float* __restrict__ ln_g, const float* __restrict__ ln_b,
    float* __restrict__ out)
{
    extern __shared__ char smc[];
    const uint32_t sb = smem_u32(smc);
    const int tid = threadIdx.x, wid = tid >> 5, lane = tid & 31;
    const int q0 = blockIdx.x * 64;

    float* xf = (float*)smc;             // 64 x 133 overlay on W
    float* zf = (float*)(smc + 34816);   // 64 x 133 overlay on W

    for (int i = tid; i < 64*128; i += 256) {
        int dd = i >> 6, ql = i & 63;
        xf[ql*133 + dd] = g_X[(size_t)dd*NN + q0 + ql];
    }
    for (int i = tid; i < 64*128; i += 256) {
        int r = i >> 7, c = i & 127;
        zf[r*133 + c] = z[(size_t)(q0 + r)*128 + c];
    }
    if (tid < 128) {
        ((float*)(smc + K3_BZ))[tid] = b_z[tid];
        ((float*)(smc + K3_BG))[tid] = b_g[tid];
    }
    __syncthreads();

    // LN(x) rows -> XH/XL
    for (int row = wid; row < 64; row += 8) {
        float s = 0.f, s2 = 0.f;
        #pragma unroll
        for (int c = lane; c < 128; c += 32) {
            float v = xf[row*133 + c];
            s += v; s2 += v*v;
        }
        #pragma unroll
        for (int o = 16; o > 0; o >>= 1) {
            s  += __shfl_xor_sync(0xffffffffu, s, o);
            s2 += __shfl_xor_sync(0xffffffffu, s2, o);
        }
        float mu = s * (1.f/128.f);
        float var = s2 * (1.f/128.f) - mu*mu;
        float rs = rsqrtf(var + 1e-5f);
        #pragma unroll
        for (int c = lane; c < 128; c += 32) {
            float v = (xf[row*133 + c] - mu) * rs * __ldg(&ln_g[c]) + __ldg(&ln_b[c]);
            __nv_bfloat16 h = __float2bfloat16(v);
            float lo = v - __bfloat162float(h);
            *(uint16_t*)(smc + K3_XH + row*PRB + c*2) = __bfloat16_as_ushort(h);
            *(uint16_t*)(smc + K3_XL + row*PRB + c*2) = __bfloat16_as_ushort(__float2bfloat16(lo));
        }
    }
    // raw z -> ZH/ZL
    for (int i = tid; i < 64*128; i += 256) {
        int r = i >> 7, c = i & 127;
        float v = zf[r*133 + c];
        __nv_bfloat16 h = __float2bfloat16(v);
        float lo = v - __bfloat162float(h);
        *(uint16_t*)(smc + K3_ZH + r*PRB + c*2) = __bfloat16_as_ushort(h);
        *(uint16_t*)(smc + K3_ZL + r*PRB + c*2) = __bfloat16_as_ushort(__float2bfloat16(lo));
    }
    __syncthreads();   // overlays dead

    // cp.async weights: [wzh, wzl, wgh, wgl]
    const uint16_t* __restrict__ wsrc[4] = { g_W3zh, g_W3zl, g_W3gh, g_W3gl };
    for (int i = tid; i < 8192; i += 256) {
        int mat = i >> 11, rem = i & 2047, row = rem >> 4, ch = rem & 15;
        cp16(sb + K3_W0 + mat*MATPB + row*PRB + ch*16, wsrc[mat] + row*128 + ch*8);
    }
    CP_COMMIT(); CP_WAIT0();
    __syncthreads();

    // MMA: warp tile 32x32 (2x4 warp grid over 64x128)
    const int wm = (wid & 1) * 32, wn = (wid >> 1) * 32;
    float accx[2][4][4], accg[2][4][4];
    #pragma unroll
    for (int a = 0; a < 2; a++)
        #pragma unroll
        for (int b = 0; b < 4; b++)
            #pragma unroll
            for (int cc = 0; cc < 4; cc++) { accx[a][b][cc] = 0.f; accg[a][b][cc] = 0.f; }

    #pragma unroll
    for (int ks = 0; ks < 8; ks++) {
        const int kb = ks * 16;
        uint32_t xh[2][4], zh[2][4], bzh[4][2], bgh[4][2];
        #pragma unroll
        for (int mf = 0; mf < 2; mf++) {
            ldsm_x4(xh[mf], addrA(sb + K3_XH, wm + mf*16, kb, lane));
            ldsm_x4(zh[mf], addrA(sb + K3_ZH, wm + mf*16, kb, lane));
        }
        #pragma unroll
        for (int nf = 0; nf < 4; nf++) {
            ldsm_x2(bzh[nf], addrB(sb + K3_W0 + 0*MATPB, wn + nf*8, kb, lane));
            ldsm_x2(bgh[nf], addrB(sb + K3_W0 + 2*MATPB, wn + nf*8, kb, lane));
        }
        #pragma unroll
        for (int mf = 0; mf < 2; mf++)
            #pragma unroll
            for (int nf = 0; nf < 4; nf++) {
                mma_bf16(accx[mf][nf], xh[mf], bzh[nf]);
                mma_bf16(accg[mf][nf], zh[mf], bgh[nf]);
            }
        {
            uint32_t bzl[4][2], bgl[4][2];
            #pragma unroll
            for (int nf = 0; nf < 4; nf++) {
                ldsm_x2(bzl[nf], addrB(sb + K3_W0 + 1*MATPB, wn + nf*8, kb, lane));
                ldsm_x2(bgl[nf], addrB(sb + K3_W0 + 3*MATPB, wn + nf*8, kb, lane));
            }
            #pragma unroll
            for (int mf = 0; mf < 2; mf++)
                #pragma unroll
                for (int nf = 0; nf < 4; nf++) {
                    mma_bf16(accx[mf][nf], xh[mf], bzl[nf]);
                    mma_bf16(accg[mf][nf], zh[mf], bgl[nf]);
                }
        }
        {
            uint32_t xl[2][4], zl[2][4];
            #pragma unroll
            for (int mf = 0; mf < 2; mf++) {
                ldsm_x4(xl[mf], addrA(sb + K3_XL, wm + mf*16, kb, lane));
                ldsm_x4(zl[mf], addrA(sb + K3_ZL, wm + mf*16, kb, lane));
            }
            #pragma unroll
            for (int mf = 0; mf < 2; mf++)
                #pragma unroll
                for (int nf = 0; nf < 4; nf++) {
                    mma_bf16(accx[mf][nf], xl[mf], bzh[nf]);
                    mma_bf16(accg[mf][nf], zl[mf], bgh[nf]);
                }
        }
    }

    // epilogue: direct stores
    float* bzv = (float*)(smc + K3_BZ);
    float* bgv = (float*)(smc + K3_BG);
    const int r = lane >> 2, cq = (lane & 3)*2;
    #pragma unroll
    for (int mf = 0; mf < 2; mf++) {
        #pragma unroll
        for (int nf = 0; nf < 4; nf++) {
            #pragma unroll
            for (int half = 0; half < 2; half++) {
                int qrow = q0 + wm + mf*16 + r + half*8;
                int col = wn + nf*8 + cq;
                float g0 = 1.f/(1.f + expf(-(accg[mf][nf][half*2+0] + bgv[col])));
                float g1 = 1.f/(1.f + expf(-(accg[mf][nf][half*2+1] + bgv[col+1])));
                float v0 = g0 * (accx[mf][nf][half*2+0] + bzv[col]);
                float v1 = g1 * (accx[mf][nf][half*2+1] + bzv[col+1]);
                *(float2*)&out[(size_t)qrow*128 + col] = make_float2(v0, v1);
            }
        }
    }
}

// ---------------------------------------------------------------------------
extern "C" void kernel_launch(void* const* d_in, const int* in_sizes, int n_in,
                              void* d_out, int out_size)
{
    const float* z        = (const float*)d_in[0];
    const float* mask     = (const float*)d_in[1];
    const float* w_ab_p   = (const float*)d_in[2];
    const float* b_ab_p   = (const float*)d_in[3];
    const float* w_ab_g   = (const float*)d_in[4];
    const float* b_ab_g   = (const float*)d_in[5];
    const float* w_g      = (const float*)d_in[6];
    const float* b_g      = (const float*)d_in[7];
    const float* w_z      = (const float*)d_in[8];
    const float* b_z      = (const float*)d_in[9];
    const float* ln_in_g  = (const float*)d_in[10];
    const float* ln_in_b  = (const float*)d_in[11];
    const float* ln_out_g = (const float*)d_in[12];
    const float* ln_out_b = (const float*)d_in[13];
    float* out = (float*)d_out;

    cudaFuncSetAttribute(k1_mma,        cudaFuncAttributeMaxDynamicSharedMemorySize, K1_SMEM);
    cudaFuncSetAttribute(k2_einsum_mma, cudaFuncAttributeMaxDynamicSharedMemorySize, K2_SMEM);
    cudaFuncSetAttribute(k3_mma,        cudaFuncAttributeMaxDynamicSharedMemorySize, K3_SMEM);

    prep_w<<<384, 256>>>(w_ab_p, w_ab_g, w_g, w_z);
    k1_mma<<<dim3(2048, 2), 256, K1_SMEM>>>(z, mask, b_ab_p, b_ab_g, ln_in_g, ln_in_b);
    k2_einsum_mma<<<dim3(4, 4, 128), 256, K2_SMEM>>>();
    k3_mma<<<4096, 256, K3_SMEM>>>(z, b_g, b_z, ln_out_g, ln_out_b, out);
}

// round 11
// speedup vs baseline: 1.0031x; 1.0029x over previous
#include <cuda_runtime.h>
#include <cuda_bf16.h>
#include <math.h>
#include <stdint.h>

#define NSZ 512
#define DSZ 128
#define NN  (NSZ*NSZ)   // 262144

// Scratch. a/b in split-bf16, d-major K-contiguous: A[d][i][k], B[d][j][k]
__device__ uint16_t g_Ah[(size_t)DSZ * NN];
__device__ uint16_t g_Al[(size_t)DSZ * NN];
__device__ uint16_t g_Bh[(size_t)DSZ * NN];
__device__ uint16_t g_Bl[(size_t)DSZ * NN];
__device__ float    g_X [(size_t)DSZ * NN];   // X[d][i][j] fp32

// Pre-split weights (hi/lo bf16)
__device__ uint16_t g_Wph[256*128], g_Wpl[256*128];   // w_ab_p
__device__ uint16_t g_Wgh[256*128], g_Wgl[256*128];   // w_ab_g
__device__ uint16_t g_W3zh[128*128], g_W3zl[128*128]; // w_z
__device__ uint16_t g_W3gh[128*128], g_W3gl[128*128]; // w_g

// ---------------------------------------------------------------------------
// helpers
// ---------------------------------------------------------------------------
__device__ __forceinline__ uint32_t smem_u32(const void* p) {
    uint32_t a;
    asm("{ .reg .u64 t; cvta.to.shared.u64 t, %1; cvt.u32.u64 %0, t; }"
        : "=r"(a) : "l"(p));
    return a;
}
__device__ __forceinline__ void ldsm_x4(uint32_t* r, uint32_t addr) {
    asm volatile("ldmatrix.sync.aligned.m8n8.x4.shared.b16 {%0,%1,%2,%3}, [%4];"
        : "=r"(r[0]), "=r"(r[1]), "=r"(r[2]), "=r"(r[3]) : "r"(addr));
}
__device__ __forceinline__ void ldsm_x2(uint32_t* r, uint32_t addr) {
    asm volatile("ldmatrix.sync.aligned.m8n8.x2.shared.b16 {%0,%1}, [%2];"
        : "=r"(r[0]), "=r"(r[1]) : "r"(addr));
}
__device__ __forceinline__ void mma_bf16(float* d, const uint32_t* a, const uint32_t* b) {
    asm volatile("mma.sync.aligned.m16n8k16.row.col.f32.bf16.bf16.f32 "
        "{%0,%1,%2,%3}, {%4,%5,%6,%7}, {%8,%9}, {%0,%1,%2,%3};"
        : "+f"(d[0]), "+f"(d[1]), "+f"(d[2]), "+f"(d[3])
        : "r"(a[0]), "r"(a[1]), "r"(a[2]), "r"(a[3]), "r"(b[0]), "r"(b[1]));
}
__device__ __forceinline__ void cp16(uint32_t dst, const void* src) {
    asm volatile("cp.async.cg.shared.global [%0], [%1], 16;" :: "r"(dst), "l"(src));
}
#define CP_COMMIT() asm volatile("cp.async.commit_group;")
#define CP_WAIT0()  asm volatile("cp.async.wait_group 0;")
#define CP_WAIT1()  asm volatile("cp.async.wait_group 1;")

// padded-row (272B) ldmatrix addressing for K=128 bf16 tiles
#define PRB 272
__device__ __forceinline__ uint32_t addrA(uint32_t base, int m, int k, int lane) {
    int g = lane >> 3;
    int row = m + ((g & 1) << 3) + (lane & 7);
    int col = k + ((g & 2) << 2);
    return base + row*PRB + col*2;
}
__device__ __forceinline__ uint32_t addrB(uint32_t base, int n, int k, int lane) {
    int g = (lane >> 3) & 1;
    int row = n + (lane & 7);
    int col = k + (g << 3);
    return base + row*PRB + col*2;
}
#define MATPB (128*PRB)   // 34816 B per 128-row matrix tile

// ---------------------------------------------------------------------------
// Kernel 0: split weights into bf16 hi/lo
// ---------------------------------------------------------------------------
__global__ void __launch_bounds__(256) prep_w(
    const float* __restrict__ wp, const float* __restrict__ wg,
    const float* __restrict__ w3g, const float* __restrict__ w3z)
{
    int idx = blockIdx.x * 256 + threadIdx.x;   // 0..98303
    float v; uint16_t* dh; uint16_t* dl; int off;
    if (idx < 32768)       { v = wp[idx];          dh = g_Wph;  dl = g_Wpl;  off = idx; }
    else if (idx < 65536)  { v = wg[idx-32768];    dh = g_Wgh;  dl = g_Wgl;  off = idx-32768; }
    else if (idx < 81920)  { v = w3g[idx-65536];   dh = g_W3gh; dl = g_W3gl; off = idx-65536; }
    else                   { v = w3z[idx-81920];   dh = g_W3zh; dl = g_W3zl; off = idx-81920; }
    __nv_bfloat16 h = __float2bfloat16(v);
    float lo = v - __bfloat162float(h);
    dh[off] = __bfloat16_as_ushort(h);
    dl[off] = __bfloat16_as_ushort(__float2bfloat16(lo));
}

// ---------------------------------------------------------------------------
// Kernel 1 (HMMA): LN(z) -> dual projection -> sigmoid gate -> mask -> split
// CTA: 128 pixels x 128 channels. grid (2048, 2). 256 thr.
// smem: W[4 mats]=139264 | ZH=34816 | ZL=34816 | mask 512 | bp 512 | bg 512
// ---------------------------------------------------------------------------
#define K1_W0   0
#define K1_ZH   139264
#define K1_ZL   174080
#define K1_MSK  208896
#define K1_BP   209408
#define K1_BG   209920
#define K1_SMEM 210432

__global__ void __launch_bounds__(256, 1) k1_mma(
    const float* __restrict__ z, const float* __restrict__ mask,
    const float* __restrict__ b_ab_p, const float* __restrict__ b_ab_g,
    const float* __restrict__ ln_g, const float* __restrict__ ln_b)
{
    extern __shared__ char smc[];
    const uint32_t sb = smem_u32(smc);
    const int tid = threadIdx.x, wid = tid >> 5, lane = tid & 31;
    const int r0 = blockIdx.x * 128;
    const int c0 = blockIdx.y * 128;

    float* zf = (float*)smc;   // overlay on W region: 128 x 132 fp32

    for (int i = tid; i < 128*128; i += 256) {
        int r = i >> 7, c = i & 127;
        zf[r*132 + c] = z[(size_t)(r0 + r)*128 + c];
    }
    if (tid < 128) {
        ((float*)(smc + K1_MSK))[tid] = mask[r0 + tid];
        ((float*)(smc + K1_BP))[tid]  = b_ab_p[c0 + tid];
        ((float*)(smc + K1_BG))[tid]  = b_ab_g[c0 + tid];
    }
    __syncthreads();

    // LN rows -> ZH/ZL bf16
    for (int row = wid; row < 128; row += 8) {
        float s = 0.f, s2 = 0.f;
        #pragma unroll
        for (int c = lane; c < 128; c += 32) {
            float v = zf[row*132 + c];
            s += v; s2 += v*v;
        }
        #pragma unroll
        for (int o = 16; o > 0; o >>= 1) {
            s  += __shfl_xor_sync(0xffffffffu, s, o);
            s2 += __shfl_xor_sync(0xffffffffu, s2, o);
        }
        float mu = s * (1.f/128.f);
        float var = s2 * (1.f/128.f) - mu*mu;
        float rs = rsqrtf(var + 1e-5f);
        #pragma unroll
        for (int c = lane; c < 128; c += 32) {
            float v = (zf[row*132 + c] - mu) * rs * __ldg(&ln_g[c]) + __ldg(&ln_b[c]);
            __nv_bfloat16 h = __float2bfloat16(v);
            float lo = v - __bfloat162float(h);
            *(uint16_t*)(smc + K1_ZH + row*PRB + c*2) = __bfloat16_as_ushort(h);
            *(uint16_t*)(smc + K1_ZL + row*PRB + c*2) = __bfloat16_as_ushort(__float2bfloat16(lo));
        }
    }
    __syncthreads();   // zf (W overlay) dead

    // cp.async weights: [phi, plo, ghi, glo] rows c0..c0+127
    const uint16_t* __restrict__ wsrc[4] = {
        g_Wph + (size_t)c0*128, g_Wpl + (size_t)c0*128,
        g_Wgh + (size_t)c0*128, g_Wgl + (size_t)c0*128 };
    for (int i = tid; i < 8192; i += 256) {
        int mat = i >> 11, rem = i & 2047, row = rem >> 4, ch = rem & 15;
        cp16(sb + K1_W0 + mat*MATPB + row*PRB + ch*16, wsrc[mat] + row*128 + ch*8);
    }
    CP_COMMIT(); CP_WAIT0();
    __syncthreads();

    // MMA: warp tile 64x32 (2x4 warp grid)
    const int wm = (wid & 1) * 64, wn = (wid >> 1) * 32;
    float accp[4][4][4], accg[4][4][4];
    #pragma unroll
    for (int a = 0; a < 4; a++)
        #pragma unroll
        for (int b = 0; b < 4; b++)
            #pragma unroll
            for (int cc = 0; cc < 4; cc++) { accp[a][b][cc] = 0.f; accg[a][b][cc] = 0.f; }

    #pragma unroll
    for (int ks = 0; ks < 8; ks++) {
        const int kb = ks * 16;
        uint32_t zh[4][4], bph[4][2], bgh[4][2];
        #pragma unroll
        for (int mf = 0; mf < 4; mf++)
            ldsm_x4(zh[mf], addrA(sb + K1_ZH, wm + mf*16, kb, lane));
        #pragma unroll
        for (int nf = 0; nf < 4; nf++) {
            ldsm_x2(bph[nf], addrB(sb + K1_W0 + 0*MATPB, wn + nf*8, kb, lane));
            ldsm_x2(bgh[nf], addrB(sb + K1_W0 + 2*MATPB, wn + nf*8, kb, lane));
        }
        #pragma unroll
        for (int mf = 0; mf < 4; mf++)
            #pragma unroll
            for (int nf = 0; nf < 4; nf++) {
                mma_bf16(accp[mf][nf], zh[mf], bph[nf]);
                mma_bf16(accg[mf][nf], zh[mf], bgh[nf]);
            }
        {
            uint32_t bpl[4][2], bgl[4][2];
            #pragma unroll
            for (int nf = 0; nf < 4; nf++) {
                ldsm_x2(bpl[nf], addrB(sb + K1_W0 + 1*MATPB, wn + nf*8, kb, lane));
                ldsm_x2(bgl[nf], addrB(sb + K1_W0 + 3*MATPB, wn + nf*8, kb, lane));
            }
            #pragma unroll
            for (int mf = 0; mf < 4; mf++)
                #pragma unroll
                for (int nf = 0; nf < 4; nf++) {
                    mma_bf16(accp[mf][nf], zh[mf], bpl[nf]);
                    mma_bf16(accg[mf][nf], zh[mf], bgl[nf]);
                }
        }
        {
            uint32_t zl[4][4];
            #pragma unroll
            for (int mf = 0; mf < 4; mf++)
                ldsm_x4(zl[mf], addrA(sb + K1_ZL, wm + mf*16, kb, lane));
            #pragma unroll
            for (int mf = 0; mf < 4; mf++)
                #pragma unroll
                for (int nf = 0; nf < 4; nf++) {
                    mma_bf16(accp[mf][nf], zl[mf], bph[nf]);
                    mma_bf16(accg[mf][nf], zl[mf], bgh[nf]);
                }
        }
    }
    __syncthreads();   // ZH/ZL dead -> reuse as stage

    // epilogue: val = (p + bp)*mask*sigmoid(g + bg), staged transposed [col][row]
    float* st  = (float*)(smc + K1_ZH);   // 128 cols x 130 stride
    float* msk = (float*)(smc + K1_MSK);
    float* bpv = (float*)(smc + K1_BP);
    float* bgv = (float*)(smc + K1_BG);
    const int r = lane >> 2, cq = (lane & 3)*2;
    #pragma unroll
    for (int mf = 0; mf < 4; mf++) {
        #pragma unroll
        for (int nf = 0; nf < 4; nf++) {
            #pragma unroll
            for (int half = 0; half < 2; half++) {
                int row = wm + mf*16 + r + half*8;
                float m = msk[row];
                #pragma unroll
                for (int q = 0; q < 2; q++) {
                    int col = wn + nf*8 + cq + q;
                    float p = accp[mf][nf][half*2 + q] + bpv[col];
                    float g = accg[mf][nf][half*2 + q] + bgv[col];
                    st[col*130 + row] = p * m * (1.f/(1.f + expf(-g)));
                }
            }
        }
    }
    __syncthreads();

    uint16_t* dh = (c0 == 0) ? g_Ah : g_Bh;
    uint16_t* dl = (c0 == 0) ? g_Al : g_Bl;
    for (int i = tid; i < 8192; i += 256) {
        int col = i >> 6, rc = i & 63;
        float v0 = st[col*130 + rc*2];
        float v1 = st[col*130 + rc*2 + 1];
        __nv_bfloat16 h0 = __float2bfloat16(v0);
        __nv_bfloat16 h1 = __float2bfloat16(v1);
        float l0 = v0 - __bfloat162float(h0);
        float l1 = v1 - __bfloat162float(h1);
        uint32_t ph = (uint32_t)__bfloat16_as_ushort(h0) |
                      ((uint32_t)__bfloat16_as_ushort(h1) << 16);
        uint32_t pl = (uint32_t)__bfloat16_as_ushort(__float2bfloat16(l0)) |
                      ((uint32_t)__bfloat16_as_ushort(__float2bfloat16(l1)) << 16);
        size_t off = (size_t)col*NN + r0 + rc*2;
        *(uint32_t*)&dh[off] = ph;
        *(uint32_t*)&dl[off] = pl;
    }
}

// ---------------------------------------------------------------------------
// Kernel 2 (HMMA): x[d][i][j] = sum_k A[d][i][k]*B[d][j][k]  (unchanged, passing)
// ---------------------------------------------------------------------------
#define KCH   32
#define ROWB  80
#define MATB  (128*ROWB)
#define BUFB  (4*MATB)
#define K2_SMEM (2*BUFB)

__device__ __forceinline__ uint32_t a2_addr(uint32_t matbase, int m, int k, int lane) {
    int g = lane >> 3;
    int row = m + ((g & 1) << 3) + (lane & 7);
    int col = k + ((g & 2) << 2);
    return matbase + row*ROWB + col*2;
}
__device__ __forceinline__ uint32_t b2_addr(uint32_t matbase, int n, int k, int lane) {
    int g = (lane >> 3) & 1;
    int row = n + (lane & 7);
    int col = k + (g << 3);
    return matbase + row*ROWB + col*2;
}

__global__ void __launch_bounds__(256, 2) k2_einsum_mma()
{
    extern __shared__ char smc[];
    const uint32_t sbase = smem_u32(smc);
    const int tid  = threadIdx.x;
    const int wid  = tid >> 5, lane = tid & 31;
    const int d  = blockIdx.z;
    const int i0 = blockIdx.y * 128;
    const int j0 = blockIdx.x * 128;
    const int wm = (wid & 1) * 64;
    const int wn = (wid >> 1) * 32;

    const uint16_t* __restrict__ srcs[4] = {
        g_Ah + (size_t)d*NN, g_Al + (size_t)d*NN,
        g_Bh + (size_t)d*NN, g_Bl + (size_t)d*NN };

    auto issue = [&](int c) {
        const uint32_t bb = sbase + (c & 1)*BUFB;
        const int k0 = c * KCH;
        #pragma unroll
        for (int i = 0; i < 8; i++) {
            int idx = tid + i*256;
            int mat = idx >> 9;
            int rem = idx & 511;
            int row = rem >> 2;
            int q   = rem & 3;
            int rbase = (mat < 2) ? i0 : j0;
            const uint16_t* s = srcs[mat] + (size_t)(rbase + row)*512 + k0 + q*8;
            cp16(bb + mat*MATB + row*ROWB + q*16, s);
        }
        CP_COMMIT();
    };

    float acc[4][4][4];
    #pragma unroll
    for (int a = 0; a < 4; a++)
        #pragma unroll
        for (int b = 0; b < 4; b++)
            #pragma unroll
            for (int cc = 0; cc < 4; cc++) acc[a][b][cc] = 0.f;

    issue(0);
    for (int c = 0; c < 16; c++) {
        if (c + 1 < 16) { issue(c + 1); CP_WAIT1(); }
        else            { CP_WAIT0(); }
        __syncthreads();

        const uint32_t bb = sbase + (c & 1)*BUFB;
        #pragma unroll
        for (int kk = 0; kk < 2; kk++) {
            const int kb = kk * 16;
            uint32_t af[4][4], bh[4][2], bl[4][2];
            #pragma unroll
            for (int mf = 0; mf < 4; mf++)
                ldsm_x4(af[mf], a2_addr(bb + 0*MATB, wm + mf*16, kb, lane));
            #pragma unroll
            for (int nf = 0; nf < 4; nf++) {
                ldsm_x2(bh[nf], b2_addr(bb + 2*MATB, wn + nf*8, kb, lane));
                ldsm_x2(bl[nf], b2_addr(bb + 3*MATB, wn + nf*8, kb, lane));
            }
            #pragma unroll
            for (int mf = 0; mf < 4; mf++)
                #pragma unroll
                for (int nf = 0; nf < 4; nf++)
                    mma_bf16(acc[mf][nf], af[mf], bh[nf]);
            #pragma unroll
            for (int mf = 0; mf < 4; mf++)
                #pragma unroll
                for (int nf = 0; nf < 4; nf++)
                    mma_bf16(acc[mf][nf], af[mf], bl[nf]);
            #pragma unroll
            for (int mf = 0; mf < 4; mf++)
                ldsm_x4(af[mf], a2_addr(bb + 1*MATB, wm + mf*16, kb, lane));
            #pragma unroll
            for (int mf = 0; mf < 4; mf++)
                #pragma unroll
                for (int nf = 0; nf < 4; nf++)
                    mma_bf16(acc[mf][nf], af[mf], bh[nf]);
        }
        __syncthreads();
    }

    float* __restrict__ X = g_X + (size_t)d * NN;
    const int r  = lane >> 2;
    const int cq = (lane & 3) * 2;
    #pragma unroll
    for (int mf = 0; mf < 4; mf++) {
        #pragma unroll
        for (int nf = 0; nf < 4; nf++) {
            size_t row0 = (size_t)(i0 + wm + mf*16 + r);
            int col = j0 + wn + nf*8 + cq;
            *(float2*)&X[row0*512 + col]       = make_float2(acc[mf][nf][0], acc[mf][nf][1]);
            *(float2*)&X[(row0 + 8)*512 + col] = make_float2(acc[mf][nf][2], acc[mf][nf][3]);
        }
    }
}

// ---------------------------------------------------------------------------
// Kernel 3 (HMMA): out = sigmoid(z·w_g^T + b_g) * (LN(x)·w_z^T + b_z)
// CTA: 64 pixels x 128 channels. grid (4096). 256 thr.
// smem: W[4]=139264 | XH 17408 | XL 17408 | ZH 17408 | ZL 17408 | bz 512 | bg 512
// ---------------------------------------------------------------------------
#define K3_W0  0
#define K3_XH  139264
#define K3_XL  156672
#define K3_ZH  174080
#define K3_ZL  191488
#define K3_BZ  208896
#define K3_BG  209408
#define K3_SMEM 209920

__global__ void __launch_bounds__(256, 1) k3_mma(
    const float* __restrict__ z,
    const float* __restrict__ b_g, const float* __restrict__ b_z,
    const float* __restrict__ ln_g, const float* __restrict__ ln_b,
    float* __restrict__ out)
{
    extern __shared__ char smc[];
    const uint32_t sb = smem_u32(smc);
    const int tid = threadIdx.x, wid = tid >> 5, lane = tid & 31;
    const int q0 = blockIdx.x * 64;

    float* xf = (float*)smc;             // 64 x 133 overlay on W
    float* zf = (float*)(smc + 34816);   // 64 x 133 overlay on W

    for (int i = tid; i < 64*128; i += 256) {
        int dd = i >> 6, ql = i & 63;
        xf[ql*133 + dd] = g_X[(size_t)dd*NN + q0 + ql];
    }
    for (int i = tid; i < 64*128; i += 256) {
        int r = i >> 7, c = i & 127;
        zf[r*133 + c] = z[(size_t)(q0 + r)*128 + c];
    }
    if (tid < 128) {
        ((float*)(smc + K3_BZ))[tid] = b_z[tid];
        ((float*)(smc + K3_BG))[tid] = b_g[tid];
    }
    __syncthreads();

    // LN(x) rows -> XH/XL
    for (int row = wid; row < 64; row += 8) {
        float s = 0.f, s2 = 0.f;
        #pragma unroll
        for (int c = lane; c < 128; c += 32) {
            float v = xf[row*133 + c];
            s += v; s2 += v*v;
        }
        #pragma unroll
        for (int o = 16; o > 0; o >>= 1) {
            s  += __shfl_xor_sync(0xffffffffu, s, o);
            s2 += __shfl_xor_sync(0xffffffffu, s2, o);
        }
        float mu = s * (1.f/128.f);
        float var = s2 * (1.f/128.f) - mu*mu;
        float rs = rsqrtf(var + 1e-5f);
        #pragma unroll
        for (int c = lane; c < 128; c += 32) {
            float v = (xf[row*133 + c] - mu) * rs * __ldg(&ln_g[c]) + __ldg(&ln_b[c]);
            __nv_bfloat16 h = __float2bfloat16(v);
            float lo = v - __bfloat162float(h);
            *(uint16_t*)(smc + K3_XH + row*PRB + c*2) = __bfloat16_as_ushort(h);
            *(uint16_t*)(smc + K3_XL + row*PRB + c*2) = __bfloat16_as_ushort(__float2bfloat16(lo));
        }
    }
    // raw z -> ZH/ZL
    for (int i = tid; i < 64*128; i += 256) {
        int r = i >> 7, c = i & 127;
        float v = zf[r*133 + c];
        __nv_bfloat16 h = __float2bfloat16(v);
        float lo = v - __bfloat162float(h);
        *(uint16_t*)(smc + K3_ZH + r*PRB + c*2) = __bfloat16_as_ushort(h);
        *(uint16_t*)(smc + K3_ZL + r*PRB + c*2) = __bfloat16_as_ushort(__float2bfloat16(lo));
    }
    __syncthreads();   // overlays dead

    // cp.async weights: [wzh, wzl, wgh, wgl]
    const uint16_t* __restrict__ wsrc[4] = { g_W3zh, g_W3zl, g_W3gh, g_W3gl };
    for (int i = tid; i < 8192; i += 256) {
        int mat = i >> 11, rem = i & 2047, row = rem >> 4, ch = rem & 15;
        cp16(sb + K3_W0 + mat*MATPB + row*PRB + ch*16, wsrc[mat] + row*128 + ch*8);
    }
    CP_COMMIT(); CP_WAIT0();
    __syncthreads();

    // MMA: warp tile 32x32 (2x4 warp grid over 64x128)
    const int wm = (wid & 1) * 32, wn = (wid >> 1) * 32;
    float accx[2][4][4], accg[2][4][4];
    #pragma unroll
    for (int a = 0; a < 2; a++)
        #pragma unroll
        for (int b = 0; b < 4; b++)
            #pragma unroll
            for (int cc = 0; cc < 4; cc++) { accx[a][b][cc] = 0.f; accg[a][b][cc] = 0.f; }

    #pragma unroll
    for (int ks = 0; ks < 8; ks++) {
        const int kb = ks * 16;
        uint32_t xh[2][4], zh[2][4], bzh[4][2], bgh[4][2];
        #pragma unroll
        for (int mf = 0; mf < 2; mf++) {
            ldsm_x4(xh[mf], addrA(sb + K3_XH, wm + mf*16, kb, lane));
            ldsm_x4(zh[mf], addrA(sb + K3_ZH, wm + mf*16, kb, lane));
        }
        #pragma unroll
        for (int nf = 0; nf < 4; nf++) {
            ldsm_x2(bzh[nf], addrB(sb + K3_W0 + 0*MATPB, wn + nf*8, kb, lane));
            ldsm_x2(bgh[nf], addrB(sb + K3_W0 + 2*MATPB, wn + nf*8, kb, lane));
        }
        #pragma unroll
        for (int mf = 0; mf < 2; mf++)
            #pragma unroll
            for (int nf = 0; nf < 4; nf++) {
                mma_bf16(accx[mf][nf], xh[mf], bzh[nf]);
                mma_bf16(accg[mf][nf], zh[mf], bgh[nf]);
            }
        {
            uint32_t bzl[4][2], bgl[4][2];
            #pragma unroll
            for (int nf = 0; nf < 4; nf++) {
                ldsm_x2(bzl[nf], addrB(sb + K3_W0 + 1*MATPB, wn + nf*8, kb, lane));
                ldsm_x2(bgl[nf], addrB(sb + K3_W0 + 3*MATPB, wn + nf*8, kb, lane));
            }
            #pragma unroll
            for (int mf = 0; mf < 2; mf++)
                #pragma unroll
                for (int nf = 0; nf < 4; nf++) {
                    mma_bf16(accx[mf][nf], xh[mf], bzl[nf]);
                    mma_bf16(accg[mf][nf], zh[mf], bgl[nf]);
                }
        }
        {
            uint32_t xl[2][4], zl[2][4];
            #pragma unroll
            for (int mf = 0; mf < 2; mf++) {
                ldsm_x4(xl[mf], addrA(sb + K3_XL, wm + mf*16, kb, lane));
                ldsm_x4(zl[mf], addrA(sb + K3_ZL, wm + mf*16, kb, lane));
            }
            #pragma unroll
            for (int mf = 0; mf < 2; mf++)
                #pragma unroll
                for (int nf = 0; nf < 4; nf++) {
                    mma_bf16(accx[mf][nf], xl[mf], bzh[nf]);
                    mma_bf16(accg[mf][nf], zl[mf], bgh[nf]);
                }
        }
    }

    // epilogue: direct stores
    float* bzv = (float*)(smc + K3_BZ);
    float* bgv = (float*)(smc + K3_BG);
    const int r = lane >> 2, cq = (lane & 3)*2;
    #pragma unroll
    for (int mf = 0; mf < 2; mf++) {
        #pragma unroll
        for (int nf = 0; nf < 4; nf++) {
            #pragma unroll
            for (int half = 0; half < 2; half++) {
                int qrow = q0 + wm + mf*16 + r + half*8;
                int col = wn + nf*8 + cq;
                float g0 = 1.f/(1.f + expf(-(accg[mf][nf][half*2+0] + bgv[col])));
                float g1 = 1.f/(1.f + expf(-(accg[mf][nf][half*2+1] + bgv[col+1])));
                float v0 = g0 * (accx[mf][nf][half*2+0] + bzv[col]);
                float v1 = g1 * (accx[mf][nf][half*2+1] + bzv[col+1]);
                *(float2*)&out[(size_t)qrow*128 + col] = make_float2(v0, v1);
            }
        }
    }
}

// ---------------------------------------------------------------------------
extern "C" void kernel_launch(void* const* d_in, const int* in_sizes, int n_in,
                              void* d_out, int out_size)
{
    const float* z        = (const float*)d_in[0];
    const float* mask     = (const float*)d_in[1];
    const float* w_ab_p   = (const float*)d_in[2];
    const float* b_ab_p   = (const float*)d_in[3];
    const float* w_ab_g   = (const float*)d_in[4];
    const float* b_ab_g   = (const float*)d_in[5];
    const float* w_g      = (const float*)d_in[6];
    const float* b_g      = (const float*)d_in[7];
    const float* w_z      = (const float*)d_in[8];
    const float* b_z      = (const float*)d_in[9];
    const float* ln_in_g  = (const float*)d_in[10];
    const float* ln_in_b  = (const float*)d_in[11];
    const float* ln_out_g = (const float*)d_in[12];
    const float* ln_out_b = (const float*)d_in[13];
    float* out = (float*)d_out;

    cudaFuncSetAttribute(k1_mma,        cudaFuncAttributeMaxDynamicSharedMemorySize, K1_SMEM);
    cudaFuncSetAttribute(k2_einsum_mma, cudaFuncAttributeMaxDynamicSharedMemorySize, K2_SMEM);
    cudaFuncSetAttribute(k3_mma,        cudaFuncAttributeMaxDynamicSharedMemorySize, K3_SMEM);

    prep_w<<<384, 256>>>(w_ab_p, w_ab_g, w_g, w_z);
    k1_mma<<<dim3(2048, 2), 256, K1_SMEM>>>(z, mask, b_ab_p, b_ab_g, ln_in_g, ln_in_b);
    k2_einsum_mma<<<dim3(4, 4, 128), 256, K2_SMEM>>>();
    k3_mma<<<4096, 256, K3_SMEM>>>(z, b_g, b_z, ln_out_g, ln_out_b, out);
}